// round 1
// baseline (speedup 1.0000x reference)
#include <cuda_runtime.h>
#include <cuda_bf16.h>
#include <math.h>

#define NN 100000
#define HID 128
#define NE 1600000
#define NC 10

// ---------------- scratch (device globals; no allocation allowed) -------------
__device__ int   g_cnt[NN];
__device__ int   g_cursor[NN];
__device__ int   g_rowptr[NN];
__device__ int   g_col[NE];
__device__ float g_invs[NN];
__device__ int   g_blockSums[256];
__device__ float g_bufA[(size_t)NN * HID];   // GEMM output (h)
__device__ float g_bufB[(size_t)NN * HID];   // aggregation output (x)

// ---------------- init ----------------
__global__ void k_zero() {
    int i = blockIdx.x * blockDim.x + threadIdx.x;
    if (i < NN) { g_cnt[i] = 0; g_cursor[i] = 0; }
}

// ---------------- degree histogram ----------------
__global__ void k_count(const int* __restrict__ dst) {
    int e = blockIdx.x * blockDim.x + threadIdx.x;
    if (e < NE) atomicAdd(&g_cnt[dst[e]], 1);
}

// ---------------- exclusive scan (3-phase) ----------------
__global__ void k_scanA() {
    __shared__ int s[512];
    int i = blockIdx.x * 512 + threadIdx.x;
    int v = (i < NN) ? g_cnt[i] : 0;
    s[threadIdx.x] = v;
    __syncthreads();
    #pragma unroll
    for (int off = 1; off < 512; off <<= 1) {
        int t = (threadIdx.x >= off) ? s[threadIdx.x - off] : 0;
        __syncthreads();
        s[threadIdx.x] += t;
        __syncthreads();
    }
    if (i < NN) g_rowptr[i] = s[threadIdx.x] - v;       // exclusive
    if (threadIdx.x == 511) g_blockSums[blockIdx.x] = s[511];
}

__global__ void k_scanB(int nblocks) {
    if (threadIdx.x == 0) {
        int acc = 0;
        for (int i = 0; i < nblocks; i++) {
            int t = g_blockSums[i];
            g_blockSums[i] = acc;
            acc += t;
        }
    }
}

__global__ void k_scanC() {
    int i = blockIdx.x * 512 + threadIdx.x;
    if (i < NN) {
        g_rowptr[i] += g_blockSums[blockIdx.x];
        // degree includes self-loop
        g_invs[i] = rsqrtf((float)(g_cnt[i] + 1));
    }
}

// ---------------- CSR scatter ----------------
__global__ void k_scatter(const int* __restrict__ src, const int* __restrict__ dst) {
    int e = blockIdx.x * blockDim.x + threadIdx.x;
    if (e < NE) {
        int d = dst[e];
        int pos = g_rowptr[d] + atomicAdd(&g_cursor[d], 1);
        g_col[pos] = src[e];
    }
}

// ---------------- SGEMM: C[M,128] = A[M,128] @ W[128,128] ----------------
// BM=128, BN=128, BK=16, 256 threads, 8x8 per-thread microtile.
// Aext == nullptr -> read g_bufB; output always g_bufA.
__global__ void k_gemm(const float* __restrict__ Aext, const float* __restrict__ W, int M) {
    const float* A = Aext ? Aext : g_bufB;
    float* C = g_bufA;

    __shared__ float As[16][128];   // transposed: As[k][m]
    __shared__ float Ws[16][128];   // Ws[k][n]

    int tid = threadIdx.x;
    int tx = tid & 15;              // col group
    int ty = tid >> 4;              // row group
    int blockRow = blockIdx.x * 128;

    float acc[8][8];
    #pragma unroll
    for (int i = 0; i < 8; i++)
        #pragma unroll
        for (int j = 0; j < 8; j++) acc[i][j] = 0.f;

    for (int k0 = 0; k0 < 128; k0 += 16) {
        #pragma unroll
        for (int l = 0; l < 2; l++) {
            int f = tid * 2 + l;              // 0..511
            // A tile: 128 rows x 4 float4
            int m  = f >> 2;
            int kq = (f & 3) * 4;
            int gr = blockRow + m;
            float4 v = make_float4(0.f, 0.f, 0.f, 0.f);
            if (gr < M) v = *(const float4*)&A[(size_t)gr * 128 + k0 + kq];
            As[kq + 0][m] = v.x;
            As[kq + 1][m] = v.y;
            As[kq + 2][m] = v.z;
            As[kq + 3][m] = v.w;
            // W tile: 16 rows x 32 float4
            int kr = f >> 5;
            int n4 = (f & 31) * 4;
            *(float4*)&Ws[kr][n4] = *(const float4*)&W[(size_t)(k0 + kr) * 128 + n4];
        }
        __syncthreads();

        #pragma unroll
        for (int k = 0; k < 16; k++) {
            float a[8], b[8];
            *(float4*)&a[0] = *(float4*)&As[k][ty * 8];
            *(float4*)&a[4] = *(float4*)&As[k][ty * 8 + 4];
            *(float4*)&b[0] = *(float4*)&Ws[k][tx * 8];
            *(float4*)&b[4] = *(float4*)&Ws[k][tx * 8 + 4];
            #pragma unroll
            for (int i = 0; i < 8; i++)
                #pragma unroll
                for (int j = 0; j < 8; j++)
                    acc[i][j] += a[i] * b[j];
        }
        __syncthreads();
    }

    #pragma unroll
    for (int i = 0; i < 8; i++) {
        int gr = blockRow + ty * 8 + i;
        if (gr < M) {
            float4 v0 = make_float4(acc[i][0], acc[i][1], acc[i][2], acc[i][3]);
            float4 v1 = make_float4(acc[i][4], acc[i][5], acc[i][6], acc[i][7]);
            *(float4*)&C[(size_t)gr * 128 + tx * 8]     = v0;
            *(float4*)&C[(size_t)gr * 128 + tx * 8 + 4] = v1;
        }
    }
}

// ---------------- gather-aggregate + bias + relu ----------------
// warp per node; lane owns float4 column slice [lane*4 .. lane*4+3].
// out[n] = relu( invs[n] * ( invs[n]*h[n] + sum_s invs[s]*h[s] ) + bias )
__global__ void k_agg(const float* __restrict__ bias) {
    const float* h = g_bufA;
    float* out = g_bufB;

    int gwarp = (blockIdx.x * blockDim.x + threadIdx.x) >> 5;
    int lane = threadIdx.x & 31;
    if (gwarp >= NN) return;
    int n = gwarp;

    float wn = g_invs[n];
    const float4* hn = (const float4*)(h + (size_t)n * 128);
    float4 hv = hn[lane];
    float ax = wn * hv.x, ay = wn * hv.y, az = wn * hv.z, aw = wn * hv.w;

    int beg = g_rowptr[n];
    int end = beg + g_cnt[n];

    for (int base = beg; base < end; base += 32) {
        int myIdx = base + lane;
        int s_my = 0;
        float w_my = 0.f;
        if (myIdx < end) {
            s_my = g_col[myIdx];
            w_my = g_invs[s_my];
        }
        int cnt = min(32, end - base);
        for (int t = 0; t < cnt; t++) {
            int   s  = __shfl_sync(0xffffffffu, s_my, t);
            float ws = __shfl_sync(0xffffffffu, w_my, t);
            float4 v = ((const float4*)(h + (size_t)s * 128))[lane];
            ax += ws * v.x; ay += ws * v.y; az += ws * v.z; aw += ws * v.w;
        }
    }

    float4 bv = ((const float4*)bias)[lane];
    float4 r;
    r.x = fmaxf(wn * ax + bv.x, 0.f);
    r.y = fmaxf(wn * ay + bv.y, 0.f);
    r.z = fmaxf(wn * az + bv.z, 0.f);
    r.w = fmaxf(wn * aw + bv.w, 0.f);
    ((float4*)(out + (size_t)n * 128))[lane] = r;
}

// ---------------- output GEMM: out[N,10] = X[N,128] @ Wout[128,10] + b ----------
__global__ void k_out(const float* __restrict__ Wout, const float* __restrict__ bout,
                      float* __restrict__ out) {
    const float* X = g_bufB;
    __shared__ float Ws[128 * NC];
    __shared__ float bs[NC];
    int tid = threadIdx.x;
    for (int i = tid; i < 128 * NC; i += blockDim.x) Ws[i] = Wout[i];
    if (tid < NC) bs[tid] = bout[tid];
    __syncthreads();

    int gwarp = (blockIdx.x * blockDim.x + tid) >> 5;
    int lane = tid & 31;
    if (gwarp >= NN) return;

    float4 xv = ((const float4*)(X + (size_t)gwarp * 128))[lane];
    int kbase = lane * 4;
    #pragma unroll
    for (int c = 0; c < NC; c++) {
        float s = xv.x * Ws[(kbase + 0) * NC + c]
                + xv.y * Ws[(kbase + 1) * NC + c]
                + xv.z * Ws[(kbase + 2) * NC + c]
                + xv.w * Ws[(kbase + 3) * NC + c];
        #pragma unroll
        for (int off = 16; off; off >>= 1)
            s += __shfl_down_sync(0xffffffffu, s, off);
        if (lane == 0) out[(size_t)gwarp * NC + c] = s + bs[c];
    }
}

// ---------------- launch ----------------
extern "C" void kernel_launch(void* const* d_in, const int* in_sizes, int n_in,
                              void* d_out, int out_size) {
    const int*   src  = (const int*)d_in[0];          // edge_index[0]
    const int*   dst  = src + NE;                     // edge_index[1]
    const float* emb  = (const float*)d_in[1];
    const float* W1   = (const float*)d_in[2];
    const float* b1   = (const float*)d_in[3];
    const float* W2   = (const float*)d_in[4];
    const float* b2   = (const float*)d_in[5];
    const float* Wout = (const float*)d_in[6];
    const float* bout = (const float*)d_in[7];
    float* out = (float*)d_out;

    const int SCAN_BLKS = (NN + 511) / 512;           // 196
    const int EDGE_BLKS = (NE + 255) / 256;           // 6250
    const int GEMM_BLKS = (NN + 127) / 128;           // 782
    const int WARP_BLKS = (NN * 32 + 255) / 256;      // 12500

    // graph structure (recomputed every launch; deterministic work)
    k_zero<<<(NN + 255) / 256, 256>>>();
    k_count<<<EDGE_BLKS, 256>>>(dst);
    k_scanA<<<SCAN_BLKS, 512>>>();
    k_scanB<<<1, 32>>>(SCAN_BLKS);
    k_scanC<<<SCAN_BLKS, 512>>>();
    k_scatter<<<EDGE_BLKS, 256>>>(src, dst);

    // layer 1
    k_gemm<<<GEMM_BLKS, 256>>>(emb, W1, NN);
    k_agg<<<WARP_BLKS, 256>>>(b1);
    // layer 2
    k_gemm<<<GEMM_BLKS, 256>>>(nullptr, W2, NN);
    k_agg<<<WARP_BLKS, 256>>>(b2);
    // output projection
    k_out<<<WARP_BLKS, 256>>>(Wout, bout, out);
}

// round 3
// speedup vs baseline: 1.3470x; 1.3470x over previous
#include <cuda_runtime.h>
#include <cuda_bf16.h>
#include <math.h>
#include <cstdint>

#define NN 100000
#define HID 128
#define NE 1600000
#define NC 10

// ---------------- scratch (device globals; no allocation allowed) -------------
__device__ int   g_cnt[NN];
__device__ int   g_cursor[NN];
__device__ int   g_rowptr[NN];
__device__ int   g_col[NE];
__device__ float g_invs[NN];
__device__ int   g_blockSums[256];
__device__ float g_bufA[(size_t)NN * HID];   // GEMM output (h)
__device__ float g_bufB[(size_t)NN * HID];   // aggregation output (x)
// bf16 hi/lo weight images, layout [n][k] (n = out-col row index, k contiguous)
__device__ uint32_t g_W1hi[128 * 64];
__device__ uint32_t g_W1lo[128 * 64];
__device__ uint32_t g_W2hi[128 * 64];
__device__ uint32_t g_W2lo[128 * 64];

// ---------------- init ----------------
__global__ void k_zero() {
    int i = blockIdx.x * blockDim.x + threadIdx.x;
    if (i < NN) { g_cnt[i] = 0; g_cursor[i] = 0; }
}

// ---------------- degree histogram ----------------
__global__ void k_count(const int* __restrict__ dst) {
    int e = blockIdx.x * blockDim.x + threadIdx.x;
    if (e < NE) atomicAdd(&g_cnt[dst[e]], 1);
}

// ---------------- exclusive scan (3-phase) ----------------
__global__ void k_scanA() {
    __shared__ int s[512];
    int i = blockIdx.x * 512 + threadIdx.x;
    int v = (i < NN) ? g_cnt[i] : 0;
    s[threadIdx.x] = v;
    __syncthreads();
    #pragma unroll
    for (int off = 1; off < 512; off <<= 1) {
        int t = (threadIdx.x >= off) ? s[threadIdx.x - off] : 0;
        __syncthreads();
        s[threadIdx.x] += t;
        __syncthreads();
    }
    if (i < NN) g_rowptr[i] = s[threadIdx.x] - v;       // exclusive
    if (threadIdx.x == 511) g_blockSums[blockIdx.x] = s[511];
}

__global__ void k_scanB(int nblocks) {
    __shared__ int s[256];
    int t = threadIdx.x;
    int v = (t < nblocks) ? g_blockSums[t] : 0;
    s[t] = v;
    __syncthreads();
    #pragma unroll
    for (int off = 1; off < 256; off <<= 1) {
        int u = (t >= off) ? s[t - off] : 0;
        __syncthreads();
        s[t] += u;
        __syncthreads();
    }
    if (t < nblocks) g_blockSums[t] = s[t] - v;          // exclusive
}

__global__ void k_scanC() {
    int i = blockIdx.x * 512 + threadIdx.x;
    if (i < NN) {
        g_rowptr[i] += g_blockSums[blockIdx.x];
        g_invs[i] = rsqrtf((float)(g_cnt[i] + 1));       // degree incl. self-loop
    }
}

// ---------------- CSR scatter ----------------
__global__ void k_scatter(const int* __restrict__ src, const int* __restrict__ dst) {
    int e = blockIdx.x * blockDim.x + threadIdx.x;
    if (e < NE) {
        int d = dst[e];
        int pos = g_rowptr[d] + atomicAdd(&g_cursor[d], 1);
        g_col[pos] = src[e];
    }
}

// ---------------- weight image precompute ----------------
// B[n][k] = W[k][n]; split fp32 -> bf16 hi + lo; store as u32 pairs (2 halves,
// consecutive k), linear layout [n][k/2].
__global__ void k_wimg(const float* __restrict__ W, int layer) {
    uint32_t* hiImg = (layer == 0 ? g_W1hi : g_W2hi);
    uint32_t* loImg = (layer == 0 ? g_W1lo : g_W2lo);
    int idx = blockIdx.x * blockDim.x + threadIdx.x;     // 0..8191 (pairs)
    if (idx >= 128 * 64) return;
    int n = idx >> 6, cp = idx & 63;
    int k0 = 2 * cp;
    float w0 = W[(size_t)k0 * HID + n];
    float w1 = W[(size_t)(k0 + 1) * HID + n];
    __nv_bfloat16 h0 = __float2bfloat16(w0), h1 = __float2bfloat16(w1);
    __nv_bfloat16 l0 = __float2bfloat16(w0 - __bfloat162float(h0));
    __nv_bfloat16 l1 = __float2bfloat16(w1 - __bfloat162float(h1));
    hiImg[idx] = (uint32_t)__bfloat16_as_ushort(h0) | ((uint32_t)__bfloat16_as_ushort(h1) << 16);
    loImg[idx] = (uint32_t)__bfloat16_as_ushort(l0) | ((uint32_t)__bfloat16_as_ushort(l1) << 16);
}

// ---------------- mma.sync bf16x3 GEMM: C[M,128] = A[M,128] @ W[128,128] -----
// 256 threads = 8 warps; warp w owns rows [w*16, w*16+16) of the 128-row tile.
// SMEM: Ahi/Alo [128][128] bf16 + Whi/Wlo [128(n)][128(k)] bf16,
// padded row stride 272 bytes (68 words) -> all fragment loads bank-conflict-free.
#define ROWW 68                            // padded row stride in u32 words
#define MAT_W (128 * ROWW)                 // words per matrix image in smem
#define DSMEM_SZ (4 * MAT_W * 4)           // bytes (139264)

__device__ __forceinline__ void mma_bf16(float* d, uint32_t a0, uint32_t a1,
                                         uint32_t a2, uint32_t a3,
                                         uint32_t b0, uint32_t b1) {
    asm volatile(
        "mma.sync.aligned.m16n8k16.row.col.f32.bf16.bf16.f32 "
        "{%0,%1,%2,%3}, {%4,%5,%6,%7}, {%8,%9}, {%0,%1,%2,%3};\n"
        : "+f"(d[0]), "+f"(d[1]), "+f"(d[2]), "+f"(d[3])
        : "r"(a0), "r"(a1), "r"(a2), "r"(a3), "r"(b0), "r"(b1));
}

__global__ void __launch_bounds__(256, 1) k_gemm_mma(const float* Aext, int layer, int M) {
    extern __shared__ uint32_t sm[];
    uint32_t* sAhi = sm;
    uint32_t* sAlo = sm + MAT_W;
    uint32_t* sWhi = sm + 2 * MAT_W;
    uint32_t* sWlo = sm + 3 * MAT_W;

    const float* A = Aext ? Aext : g_bufB;
    float* C = g_bufA;
    const uint32_t* whi = (layer == 0 ? g_W1hi : g_W2hi);
    const uint32_t* wlo = (layer == 0 ? g_W1lo : g_W2lo);

    int tid = threadIdx.x;
    int wid = tid >> 5, lane = tid & 31;
    int g = lane >> 2, t = lane & 3;
    int blockRow = blockIdx.x * 128;

    // Stage W images (linear -> padded rows)
    #pragma unroll
    for (int i = 0; i < 32; i++) {
        int idx = tid + i * 256;            // 0..8191
        int row = idx >> 6, c = idx & 63;
        sWhi[row * ROWW + c] = whi[idx];
        sWlo[row * ROWW + c] = wlo[idx];
    }

    // Convert A tile fp32 -> bf16 hi/lo into padded rows
    #pragma unroll
    for (int i = 0; i < 32; i++) {
        int idx = tid + i * 256;            // pair index
        int row = idx >> 6, c = idx & 63;
        int gr = blockRow + row;
        float2 v = make_float2(0.f, 0.f);
        if (gr < M) v = *(const float2*)&A[(size_t)gr * HID + 2 * c];
        __nv_bfloat16 h0 = __float2bfloat16(v.x), h1 = __float2bfloat16(v.y);
        __nv_bfloat16 l0 = __float2bfloat16(v.x - __bfloat162float(h0));
        __nv_bfloat16 l1 = __float2bfloat16(v.y - __bfloat162float(h1));
        sAhi[row * ROWW + c] = (uint32_t)__bfloat16_as_ushort(h0) | ((uint32_t)__bfloat16_as_ushort(h1) << 16);
        sAlo[row * ROWW + c] = (uint32_t)__bfloat16_as_ushort(l0) | ((uint32_t)__bfloat16_as_ushort(l1) << 16);
    }
    __syncthreads();

    float acc[16][4];
    #pragma unroll
    for (int j = 0; j < 16; j++)
        #pragma unroll
        for (int q = 0; q < 4; q++) acc[j][q] = 0.f;

    int rowA0 = (wid * 16 + g) * ROWW;      // word offset of row (warp stripe)
    int rowA1 = rowA0 + 8 * ROWW;

    #pragma unroll
    for (int pass = 0; pass < 3; pass++) {
        const uint32_t* Ab = (pass == 1) ? sAlo : sAhi;
        const uint32_t* Wb = (pass == 2) ? sWlo : sWhi;
        #pragma unroll
        for (int kc = 0; kc < 8; kc++) {
            int kw = kc * 8 + t;            // word offset of k = kc*16 + 2t
            uint32_t a0 = Ab[rowA0 + kw];
            uint32_t a1 = Ab[rowA1 + kw];
            uint32_t a2 = Ab[rowA0 + kw + 4];
            uint32_t a3 = Ab[rowA1 + kw + 4];
            #pragma unroll
            for (int j = 0; j < 16; j++) {
                int rb = (j * 8 + g) * ROWW + kw;
                uint32_t b0 = Wb[rb];
                uint32_t b1 = Wb[rb + 4];
                mma_bf16(acc[j], a0, a1, a2, a3, b0, b1);
            }
        }
    }

    // Epilogue: d0,d1 -> (row g, cols 2t,2t+1); d2,d3 -> (row g+8)
    int gr0 = blockRow + wid * 16 + g;
    int gr1 = gr0 + 8;
    #pragma unroll
    for (int j = 0; j < 16; j++) {
        int col = j * 8 + 2 * t;
        if (gr0 < M) *(float2*)&C[(size_t)gr0 * HID + col] = make_float2(acc[j][0], acc[j][1]);
        if (gr1 < M) *(float2*)&C[(size_t)gr1 * HID + col] = make_float2(acc[j][2], acc[j][3]);
    }
}

// ---------------- gather-aggregate + bias + relu (+ fused output proj) -------
__global__ void k_agg(const float* __restrict__ bias,
                      const float* __restrict__ Wout, const float* __restrict__ bout,
                      float* __restrict__ out) {
    const float* h = g_bufA;
    __shared__ float Ws[HID * NC];
    __shared__ float bs[NC];

    int tid = threadIdx.x;
    if (Wout) {
        for (int i = tid; i < HID * NC; i += blockDim.x) Ws[i] = Wout[i];
        if (tid < NC) bs[tid] = bout[tid];
        __syncthreads();
    }

    int gwarp = (blockIdx.x * blockDim.x + tid) >> 5;
    int lane = tid & 31;
    int n = gwarp;                           // grid exact: 100000 warps

    float wn = g_invs[n];
    float4 hv = ((const float4*)(h + (size_t)n * HID))[lane];
    float ax = wn * hv.x, ay = wn * hv.y, az = wn * hv.z, aw = wn * hv.w;

    int beg = g_rowptr[n];
    int end = beg + g_cnt[n];

    for (int base = beg; base < end; base += 32) {
        int myIdx = base + lane;
        int s_my = 0;
        float w_my = 0.f;
        if (myIdx < end) {
            s_my = g_col[myIdx];
            w_my = g_invs[s_my];
        }
        int cnt = min(32, end - base);
        for (int tt = 0; tt < cnt; tt++) {
            int   s  = __shfl_sync(0xffffffffu, s_my, tt);
            float ws = __shfl_sync(0xffffffffu, w_my, tt);
            float4 v = ((const float4*)(h + (size_t)s * HID))[lane];
            ax += ws * v.x; ay += ws * v.y; az += ws * v.z; aw += ws * v.w;
        }
    }

    float4 bv = ((const float4*)bias)[lane];
    float4 r;
    r.x = fmaxf(wn * ax + bv.x, 0.f);
    r.y = fmaxf(wn * ay + bv.y, 0.f);
    r.z = fmaxf(wn * az + bv.z, 0.f);
    r.w = fmaxf(wn * aw + bv.w, 0.f);

    if (!Wout) {
        ((float4*)(g_bufB + (size_t)n * HID))[lane] = r;
    } else {
        int kb = lane * 4;
        #pragma unroll
        for (int c = 0; c < NC; c++) {
            float s = r.x * Ws[(kb + 0) * NC + c]
                    + r.y * Ws[(kb + 1) * NC + c]
                    + r.z * Ws[(kb + 2) * NC + c]
                    + r.w * Ws[(kb + 3) * NC + c];
            #pragma unroll
            for (int off = 16; off; off >>= 1)
                s += __shfl_down_sync(0xffffffffu, s, off);
            if (lane == 0) out[(size_t)n * NC + c] = s + bs[c];
        }
    }
}

// ---------------- launch ----------------
extern "C" void kernel_launch(void* const* d_in, const int* in_sizes, int n_in,
                              void* d_out, int out_size) {
    const int*   src  = (const int*)d_in[0];          // edge_index[0]
    const int*   dst  = src + NE;                     // edge_index[1]
    const float* emb  = (const float*)d_in[1];
    const float* W1   = (const float*)d_in[2];
    const float* b1   = (const float*)d_in[3];
    const float* W2   = (const float*)d_in[4];
    const float* b2   = (const float*)d_in[5];
    const float* Wout = (const float*)d_in[6];
    const float* bout = (const float*)d_in[7];
    float* out = (float*)d_out;

    const int SCAN_BLKS = (NN + 511) / 512;           // 196
    const int EDGE_BLKS = (NE + 255) / 256;           // 6250
    const int GEMM_BLKS = (NN + 127) / 128;           // 782
    const int WARP_BLKS = (NN * 32) / 256;            // 12500 (exact)

    static bool attr_set = false;
    if (!attr_set) {
        cudaFuncSetAttribute(k_gemm_mma, cudaFuncAttributeMaxDynamicSharedMemorySize, DSMEM_SZ);
        attr_set = true;
    }

    // graph structure + weight images (deterministic, every launch)
    k_zero<<<(NN + 255) / 256, 256>>>();
    k_wimg<<<32, 256>>>(W1, 0);
    k_wimg<<<32, 256>>>(W2, 1);
    k_count<<<EDGE_BLKS, 256>>>(dst);
    k_scanA<<<SCAN_BLKS, 512>>>();
    k_scanB<<<1, 256>>>(SCAN_BLKS);
    k_scanC<<<SCAN_BLKS, 512>>>();
    k_scatter<<<EDGE_BLKS, 256>>>(src, dst);

    // layer 1
    k_gemm_mma<<<GEMM_BLKS, 256, DSMEM_SZ>>>(emb, 0, NN);
    k_agg<<<WARP_BLKS, 256>>>(b1, nullptr, nullptr, nullptr);
    // layer 2 (+ fused output projection)
    k_gemm_mma<<<GEMM_BLKS, 256, DSMEM_SZ>>>(nullptr, 1, NN);
    k_agg<<<WARP_BLKS, 256>>>(b2, Wout, bout, out);
}

// round 4
// speedup vs baseline: 1.6759x; 1.2441x over previous
#include <cuda_runtime.h>
#include <cuda_bf16.h>
#include <cuda_fp16.h>
#include <math.h>
#include <cstdint>

#define NN 100000
#define HID 128
#define NE 1600000
#define NC 10

// ---------------- scratch (device globals; no allocation allowed) -------------
__device__ int    g_cnt[NN];
__device__ int    g_cursor[NN];
__device__ int    g_rowptr[NN];
__device__ int    g_col[NE];
__device__ float  g_invs[NN];
__device__ int    g_blockSums[256];
__device__ __half g_bufH[(size_t)NN * HID];  // GEMM output, pre-scaled: h' = invs*h (fp16)
__device__ float  g_bufB[(size_t)NN * HID];  // aggregation output (x, fp32)
// bf16 hi/lo weight images, layout [n][k/2] u32 pairs
__device__ uint32_t g_W1hi[128 * 64];
__device__ uint32_t g_W1lo[128 * 64];
__device__ uint32_t g_W2hi[128 * 64];
__device__ uint32_t g_W2lo[128 * 64];

// ---------------- init ----------------
__global__ void k_zero() {
    int i = blockIdx.x * blockDim.x + threadIdx.x;
    if (i < NN) { g_cnt[i] = 0; g_cursor[i] = 0; }
}

// ---------------- degree histogram (int4 vectorized) ----------------
__global__ void k_count(const int* __restrict__ dst) {
    int e4 = blockIdx.x * blockDim.x + threadIdx.x;
    if (e4 < NE / 4) {
        int4 d = ((const int4*)dst)[e4];
        atomicAdd(&g_cnt[d.x], 1);
        atomicAdd(&g_cnt[d.y], 1);
        atomicAdd(&g_cnt[d.z], 1);
        atomicAdd(&g_cnt[d.w], 1);
    }
}

// ---------------- exclusive scan (3-phase) ----------------
__global__ void k_scanA() {
    __shared__ int s[512];
    int i = blockIdx.x * 512 + threadIdx.x;
    int v = (i < NN) ? g_cnt[i] : 0;
    s[threadIdx.x] = v;
    __syncthreads();
    #pragma unroll
    for (int off = 1; off < 512; off <<= 1) {
        int t = (threadIdx.x >= off) ? s[threadIdx.x - off] : 0;
        __syncthreads();
        s[threadIdx.x] += t;
        __syncthreads();
    }
    if (i < NN) g_rowptr[i] = s[threadIdx.x] - v;       // exclusive
    if (threadIdx.x == 511) g_blockSums[blockIdx.x] = s[511];
}

__global__ void k_scanB(int nblocks) {
    __shared__ int s[256];
    int t = threadIdx.x;
    int v = (t < nblocks) ? g_blockSums[t] : 0;
    s[t] = v;
    __syncthreads();
    #pragma unroll
    for (int off = 1; off < 256; off <<= 1) {
        int u = (t >= off) ? s[t - off] : 0;
        __syncthreads();
        s[t] += u;
        __syncthreads();
    }
    if (t < nblocks) g_blockSums[t] = s[t] - v;          // exclusive
}

__global__ void k_scanC() {
    int i = blockIdx.x * 512 + threadIdx.x;
    if (i < NN) {
        g_rowptr[i] += g_blockSums[blockIdx.x];
        g_invs[i] = rsqrtf((float)(g_cnt[i] + 1));       // degree incl. self-loop
    }
}

// ---------------- CSR scatter (int4 vectorized) ----------------
__global__ void k_scatter(const int* __restrict__ src, const int* __restrict__ dst) {
    int e4 = blockIdx.x * blockDim.x + threadIdx.x;
    if (e4 < NE / 4) {
        int4 s = ((const int4*)src)[e4];
        int4 d = ((const int4*)dst)[e4];
        g_col[g_rowptr[d.x] + atomicAdd(&g_cursor[d.x], 1)] = s.x;
        g_col[g_rowptr[d.y] + atomicAdd(&g_cursor[d.y], 1)] = s.y;
        g_col[g_rowptr[d.z] + atomicAdd(&g_cursor[d.z], 1)] = s.z;
        g_col[g_rowptr[d.w] + atomicAdd(&g_cursor[d.w], 1)] = s.w;
    }
}

// ---------------- weight image precompute ----------------
__global__ void k_wimg(const float* __restrict__ W, int layer) {
    uint32_t* hiImg = (layer == 0 ? g_W1hi : g_W2hi);
    uint32_t* loImg = (layer == 0 ? g_W1lo : g_W2lo);
    int idx = blockIdx.x * blockDim.x + threadIdx.x;     // 0..8191 (pairs)
    if (idx >= 128 * 64) return;
    int n = idx >> 6, cp = idx & 63;
    int k0 = 2 * cp;
    float w0 = W[(size_t)k0 * HID + n];
    float w1 = W[(size_t)(k0 + 1) * HID + n];
    __nv_bfloat16 h0 = __float2bfloat16(w0), h1 = __float2bfloat16(w1);
    __nv_bfloat16 l0 = __float2bfloat16(w0 - __bfloat162float(h0));
    __nv_bfloat16 l1 = __float2bfloat16(w1 - __bfloat162float(h1));
    hiImg[idx] = (uint32_t)__bfloat16_as_ushort(h0) | ((uint32_t)__bfloat16_as_ushort(h1) << 16);
    loImg[idx] = (uint32_t)__bfloat16_as_ushort(l0) | ((uint32_t)__bfloat16_as_ushort(l1) << 16);
}

// ---------------- mma.sync bf16x3 GEMM -> fp16 pre-scaled output -------------
// C'[r][:] = invs[r] * (A[r][:] @ W)  stored fp16.
#define ROWW 68
#define MAT_W (128 * ROWW)
#define DSMEM_SZ (4 * MAT_W * 4)

__device__ __forceinline__ void mma_bf16(float* d, uint32_t a0, uint32_t a1,
                                         uint32_t a2, uint32_t a3,
                                         uint32_t b0, uint32_t b1) {
    asm volatile(
        "mma.sync.aligned.m16n8k16.row.col.f32.bf16.bf16.f32 "
        "{%0,%1,%2,%3}, {%4,%5,%6,%7}, {%8,%9}, {%0,%1,%2,%3};\n"
        : "+f"(d[0]), "+f"(d[1]), "+f"(d[2]), "+f"(d[3])
        : "r"(a0), "r"(a1), "r"(a2), "r"(a3), "r"(b0), "r"(b1));
}

__global__ void __launch_bounds__(256, 1) k_gemm_mma(const float* Aext, int layer, int M) {
    extern __shared__ uint32_t sm[];
    uint32_t* sAhi = sm;
    uint32_t* sAlo = sm + MAT_W;
    uint32_t* sWhi = sm + 2 * MAT_W;
    uint32_t* sWlo = sm + 3 * MAT_W;

    const float* A = Aext ? Aext : g_bufB;
    const uint32_t* whi = (layer == 0 ? g_W1hi : g_W2hi);
    const uint32_t* wlo = (layer == 0 ? g_W1lo : g_W2lo);

    int tid = threadIdx.x;
    int wid = tid >> 5, lane = tid & 31;
    int g = lane >> 2, t = lane & 3;
    int blockRow = blockIdx.x * 128;

    // Stage W images
    #pragma unroll
    for (int i = 0; i < 32; i++) {
        int idx = tid + i * 256;
        int row = idx >> 6, c = idx & 63;
        sWhi[row * ROWW + c] = whi[idx];
        sWlo[row * ROWW + c] = wlo[idx];
    }

    // Convert A tile fp32 -> bf16 hi/lo
    #pragma unroll
    for (int i = 0; i < 32; i++) {
        int idx = tid + i * 256;
        int row = idx >> 6, c = idx & 63;
        int gr = blockRow + row;
        float2 v = make_float2(0.f, 0.f);
        if (gr < M) v = *(const float2*)&A[(size_t)gr * HID + 2 * c];
        __nv_bfloat16 h0 = __float2bfloat16(v.x), h1 = __float2bfloat16(v.y);
        __nv_bfloat16 l0 = __float2bfloat16(v.x - __bfloat162float(h0));
        __nv_bfloat16 l1 = __float2bfloat16(v.y - __bfloat162float(h1));
        sAhi[row * ROWW + c] = (uint32_t)__bfloat16_as_ushort(h0) | ((uint32_t)__bfloat16_as_ushort(h1) << 16);
        sAlo[row * ROWW + c] = (uint32_t)__bfloat16_as_ushort(l0) | ((uint32_t)__bfloat16_as_ushort(l1) << 16);
    }
    __syncthreads();

    float acc[16][4];
    #pragma unroll
    for (int j = 0; j < 16; j++)
        #pragma unroll
        for (int q = 0; q < 4; q++) acc[j][q] = 0.f;

    int rowA0 = (wid * 16 + g) * ROWW;
    int rowA1 = rowA0 + 8 * ROWW;

    // Fragment-reuse mainloop: per k-chunk load A frags once, W frags once per j
    #pragma unroll
    for (int kc = 0; kc < 8; kc++) {
        int kw = kc * 8 + t;
        uint32_t ah0 = sAhi[rowA0 + kw], ah1 = sAhi[rowA1 + kw];
        uint32_t ah2 = sAhi[rowA0 + kw + 4], ah3 = sAhi[rowA1 + kw + 4];
        uint32_t al0 = sAlo[rowA0 + kw], al1 = sAlo[rowA1 + kw];
        uint32_t al2 = sAlo[rowA0 + kw + 4], al3 = sAlo[rowA1 + kw + 4];
        #pragma unroll
        for (int j = 0; j < 16; j++) {
            int rb = (j * 8 + g) * ROWW + kw;
            uint32_t bh0 = sWhi[rb], bh1 = sWhi[rb + 4];
            uint32_t bl0 = sWlo[rb], bl1 = sWlo[rb + 4];
            mma_bf16(acc[j], ah0, ah1, ah2, ah3, bh0, bh1);
            mma_bf16(acc[j], al0, al1, al2, al3, bh0, bh1);
            mma_bf16(acc[j], ah0, ah1, ah2, ah3, bl0, bl1);
        }
    }

    // Epilogue: scale by invs[row], store fp16
    int gr0 = blockRow + wid * 16 + g;
    int gr1 = gr0 + 8;
    float wn0 = (gr0 < M) ? g_invs[gr0] : 0.f;
    float wn1 = (gr1 < M) ? g_invs[gr1] : 0.f;
    #pragma unroll
    for (int j = 0; j < 16; j++) {
        int col = j * 8 + 2 * t;
        if (gr0 < M)
            *(__half2*)&g_bufH[(size_t)gr0 * HID + col] =
                __floats2half2_rn(wn0 * acc[j][0], wn0 * acc[j][1]);
        if (gr1 < M)
            *(__half2*)&g_bufH[(size_t)gr1 * HID + col] =
                __floats2half2_rn(wn1 * acc[j][2], wn1 * acc[j][3]);
    }
}

// ---------------- gather-aggregate + bias + relu (+ fused output proj) -------
// agg[n] = invs[n] * sum_{s in N(n) U {n}} h'[s];  x = relu(agg + bias)
__global__ void k_agg(const float* __restrict__ bias,
                      const float* __restrict__ Wout, const float* __restrict__ bout,
                      float* __restrict__ out) {
    const __half* h = g_bufH;
    __shared__ float Ws[HID * NC];
    __shared__ float bs[NC];

    int tid = threadIdx.x;
    if (Wout) {
        for (int i = tid; i < HID * NC; i += blockDim.x) Ws[i] = Wout[i];
        if (tid < NC) bs[tid] = bout[tid];
        __syncthreads();
    }

    int n = (blockIdx.x * blockDim.x + tid) >> 5;    // grid exact: 100000 warps
    int lane = tid & 31;

    // lane owns 4 columns [lane*4 .. lane*4+3] -> uint2 of half2s
    const uint2* hrow;
    float ax, ay, az, aw;
    {
        hrow = (const uint2*)(h + (size_t)n * HID);
        uint2 v = hrow[lane];
        float2 p0 = __half22float2(*(const __half2*)&v.x);
        float2 p1 = __half22float2(*(const __half2*)&v.y);
        ax = p0.x; ay = p0.y; az = p1.x; aw = p1.y;   // self term h'[n]
    }

    int beg = g_rowptr[n];
    int end = beg + g_cnt[n];

    int idx = beg;
    for (; idx + 1 < end; idx += 2) {                 // 2-way MLP
        int s0 = g_col[idx];
        int s1 = g_col[idx + 1];
        uint2 v0 = ((const uint2*)(h + (size_t)s0 * HID))[lane];
        uint2 v1 = ((const uint2*)(h + (size_t)s1 * HID))[lane];
        float2 a0 = __half22float2(*(const __half2*)&v0.x);
        float2 b0 = __half22float2(*(const __half2*)&v0.y);
        float2 a1 = __half22float2(*(const __half2*)&v1.x);
        float2 b1 = __half22float2(*(const __half2*)&v1.y);
        ax += a0.x + a1.x; ay += a0.y + a1.y;
        az += b0.x + b1.x; aw += b0.y + b1.y;
    }
    if (idx < end) {
        int s0 = g_col[idx];
        uint2 v0 = ((const uint2*)(h + (size_t)s0 * HID))[lane];
        float2 a0 = __half22float2(*(const __half2*)&v0.x);
        float2 b0 = __half22float2(*(const __half2*)&v0.y);
        ax += a0.x; ay += a0.y; az += b0.x; aw += b0.y;
    }

    float wn = g_invs[n];
    float4 bv = ((const float4*)bias)[lane];
    float4 r;
    r.x = fmaxf(wn * ax + bv.x, 0.f);
    r.y = fmaxf(wn * ay + bv.y, 0.f);
    r.z = fmaxf(wn * az + bv.z, 0.f);
    r.w = fmaxf(wn * aw + bv.w, 0.f);

    if (!Wout) {
        ((float4*)(g_bufB + (size_t)n * HID))[lane] = r;
    } else {
        int kb = lane * 4;
        #pragma unroll
        for (int c = 0; c < NC; c++) {
            float s = r.x * Ws[(kb + 0) * NC + c]
                    + r.y * Ws[(kb + 1) * NC + c]
                    + r.z * Ws[(kb + 2) * NC + c]
                    + r.w * Ws[(kb + 3) * NC + c];
            #pragma unroll
            for (int off = 16; off; off >>= 1)
                s += __shfl_down_sync(0xffffffffu, s, off);
            if (lane == 0) out[(size_t)n * NC + c] = s + bs[c];
        }
    }
}

// ---------------- launch ----------------
extern "C" void kernel_launch(void* const* d_in, const int* in_sizes, int n_in,
                              void* d_out, int out_size) {
    const int*   src  = (const int*)d_in[0];          // edge_index[0]
    const int*   dst  = src + NE;                     // edge_index[1]
    const float* emb  = (const float*)d_in[1];
    const float* W1   = (const float*)d_in[2];
    const float* b1   = (const float*)d_in[3];
    const float* W2   = (const float*)d_in[4];
    const float* b2   = (const float*)d_in[5];
    const float* Wout = (const float*)d_in[6];
    const float* bout = (const float*)d_in[7];
    float* out = (float*)d_out;

    const int SCAN_BLKS  = (NN + 511) / 512;          // 196
    const int EDGE4_BLKS = (NE / 4 + 255) / 256;      // 1563
    const int GEMM_BLKS  = (NN + 127) / 128;          // 782
    const int WARP_BLKS  = (NN * 32) / 256;           // 12500 (exact)

    static bool attr_set = false;
    if (!attr_set) {
        cudaFuncSetAttribute(k_gemm_mma, cudaFuncAttributeMaxDynamicSharedMemorySize, DSMEM_SZ);
        attr_set = true;
    }

    // graph structure + weight images (deterministic, every launch)
    k_zero<<<(NN + 255) / 256, 256>>>();
    k_wimg<<<32, 256>>>(W1, 0);
    k_wimg<<<32, 256>>>(W2, 1);
    k_count<<<EDGE4_BLKS, 256>>>(dst);
    k_scanA<<<SCAN_BLKS, 512>>>();
    k_scanB<<<1, 256>>>(SCAN_BLKS);
    k_scanC<<<SCAN_BLKS, 512>>>();
    k_scatter<<<EDGE4_BLKS, 256>>>(src, dst);

    // layer 1
    k_gemm_mma<<<GEMM_BLKS, 256, DSMEM_SZ>>>(emb, 0, NN);
    k_agg<<<WARP_BLKS, 256>>>(b1, nullptr, nullptr, nullptr);
    // layer 2 (+ fused output projection)
    k_gemm_mma<<<GEMM_BLKS, 256, DSMEM_SZ>>>(nullptr, 1, NN);
    k_agg<<<WARP_BLKS, 256>>>(b2, Wout, bout, out);
}